// round 1
// baseline (speedup 1.0000x reference)
#include <cuda_runtime.h>
#include <cuda_bf16.h>
#include <math.h>

#define BB 32      // batch
#define DD 128     // dim
#define RR 32      // relations
#define N_TOT 32768
#define TN 128     // n-rows per block in score kernel

// ---------------- scratch (no allocations allowed) ----------------
__device__ float g_scores[BB * N_TOT];   // 4MB
__device__ float g_qb[BB * DD];          // qh + b1

// ---------------- kernel A: qb[b,d] = (query @ w1q)[b,d] + b1[d] ----------------
__global__ void qb_kernel(const float* __restrict__ query,
                          const float* __restrict__ w1,
                          const float* __restrict__ b1) {
    int b = blockIdx.x, d = threadIdx.x;
    __shared__ float sq[DD];
    sq[d] = query[b * DD + d];
    __syncthreads();
    float acc = b1[d];
#pragma unroll 8
    for (int k = 0; k < DD; k++) acc += sq[k] * __ldg(&w1[k * DD + d]);
    g_qb[b * DD + d] = acc;
}

// ---------------- kernel B: fused body-build + GEMM + relu-dot score ----------------
// smem layout (floats):
//   [0, 16896)         region0: bodyT[128][128] during GEMM, then bh[128][132]
//   [16896, 33280)     sW[d][o]  (w1b)
//   [33280, 37408)     sRel[32][129]  (padded, conflict-free column reads)
//   [37408, 41504)     sQb[32][128]
//   [41504, 41632)     sW2[128]
#define OFF_W   16896
#define OFF_REL 33280
#define OFF_QB  37408
#define OFF_W2  41504
#define SMEM_FLOATS 41632
#define SMEM_BYTES (SMEM_FLOATS * 4)

__global__ __launch_bounds__(256, 1)
void score_kernel(const float* __restrict__ rel,
                  const float* __restrict__ w1,
                  const float* __restrict__ w2) {
    extern __shared__ float sm[];
    float* sBT  = sm;            // bodyT: [d][nn], 128x128
    float* sW   = sm + OFF_W;    // [d][o]
    float* sRel = sm + OFF_REL;  // [r][129]
    float* sQb  = sm + OFF_QB;   // [b][128]
    float* sW2  = sm + OFF_W2;
    float* sBH  = sm;            // bh: [nn][132] (reuses region0 after GEMM)

    int tid = threadIdx.x;
    int n0  = blockIdx.x * TN;

    // cooperative loads
    const float* w1b = w1 + DD * DD;   // second half of w1
    for (int idx = tid; idx < DD * DD; idx += 256) sW[idx] = w1b[idx];
    for (int idx = tid; idx < RR * DD; idx += 256) {
        int r = idx >> 7, d = idx & 127;
        sRel[r * 129 + d] = rel[idx];
    }
    for (int idx = tid; idx < BB * DD; idx += 256) sQb[idx] = g_qb[idx];
    if (tid < DD) sW2[tid] = w2[tid];
    __syncthreads();

    // body^T tile: bodyT[d][nn] = rel[i][d]*rel[j][d]*rel[k][d]
    int iblk = n0 >> 10;   // i is constant within a 128-row tile
    for (int idx = tid; idx < TN * DD; idx += 256) {
        int d = idx >> 7, nn = idx & 127;
        int n = n0 + nn;
        int j = (n >> 5) & 31, k = n & 31;
        sBT[d * TN + nn] = sRel[iblk * 129 + d] * sRel[j * 129 + d] * sRel[k * 129 + d];
    }
    __syncthreads();

    // 128x128x128 GEMM, 16x16 threads, 8x8 microtile
    int ty = tid >> 4, tx = tid & 15;
    float acc[8][8];
#pragma unroll
    for (int u = 0; u < 8; u++)
#pragma unroll
        for (int v = 0; v < 8; v++) acc[u][v] = 0.0f;

    for (int kk = 0; kk < DD; kk++) {
        float4 a0 = *(const float4*)&sBT[kk * TN + (ty << 3)];
        float4 a1 = *(const float4*)&sBT[kk * TN + (ty << 3) + 4];
        float4 b0 = *(const float4*)&sW[kk * DD + (tx << 3)];
        float4 b1 = *(const float4*)&sW[kk * DD + (tx << 3) + 4];
        float a[8] = {a0.x, a0.y, a0.z, a0.w, a1.x, a1.y, a1.z, a1.w};
        float bv[8] = {b0.x, b0.y, b0.z, b0.w, b1.x, b1.y, b1.z, b1.w};
#pragma unroll
        for (int u = 0; u < 8; u++)
#pragma unroll
            for (int v = 0; v < 8; v++) acc[u][v] = fmaf(a[u], bv[v], acc[u][v]);
    }
    __syncthreads();   // all done reading sBT

    // write bh tile to smem [nn][132] (pad keeps float4 rows aligned + conflict-free)
#pragma unroll
    for (int u = 0; u < 8; u++) {
        int nn = (ty << 3) + u;
        float4 lo = make_float4(acc[u][0], acc[u][1], acc[u][2], acc[u][3]);
        float4 hi = make_float4(acc[u][4], acc[u][5], acc[u][6], acc[u][7]);
        *(float4*)&sBH[nn * 132 + (tx << 3)]     = lo;
        *(float4*)&sBH[nn * 132 + (tx << 3) + 4] = hi;
    }
    __syncthreads();

    // scores: thread owns (b = tid>>3, n = g + 8*s, s=0..15)
    int b = tid >> 3, g = tid & 7;
    float sc[16];
#pragma unroll
    for (int s = 0; s < 16; s++) sc[s] = 0.0f;
    const float4* qb4 = (const float4*)&sQb[b * DD];
    const float4* w24 = (const float4*)sW2;
    for (int d4 = 0; d4 < 32; d4++) {
        float4 qv = qb4[d4];
        float4 wv = w24[d4];
#pragma unroll
        for (int s = 0; s < 16; s++) {
            int nn = g + (s << 3);
            float4 bh = *(const float4*)&sBH[nn * 132 + (d4 << 2)];
            sc[s] += fmaxf(qv.x + bh.x, 0.0f) * wv.x
                   + fmaxf(qv.y + bh.y, 0.0f) * wv.y
                   + fmaxf(qv.z + bh.z, 0.0f) * wv.z
                   + fmaxf(qv.w + bh.w, 0.0f) * wv.w;
        }
    }
#pragma unroll
    for (int s = 0; s < 16; s++)
        g_scores[b * N_TOT + n0 + g + (s << 3)] = sc[s];
}

// ---------------- kernel C: softmax + marginals + subgoals ----------------
__global__ __launch_bounds__(1024)
void softmax_kernel(const float* __restrict__ rel,
                    float* __restrict__ out, int out_size) {
    int b = blockIdx.x;
    int tid = threadIdx.x;
    int lane = tid & 31, wid = tid >> 5;
    __shared__ float sRed[32];
    __shared__ float sA0[32], sA1[32], sA2[32];
    __shared__ float sM, sZ;
    const float* s = g_scores + b * N_TOT;

    // pass 1: row max
    float m = -3.402823466e38f;
    for (int it = 0; it < 32; it++) m = fmaxf(m, s[tid + (it << 10)]);
#pragma unroll
    for (int o = 16; o; o >>= 1) m = fmaxf(m, __shfl_xor_sync(0xffffffffu, m, o));
    if (lane == 0) sRed[wid] = m;
    if (tid < 32) { sA0[tid] = 0.0f; sA1[tid] = 0.0f; sA2[tid] = 0.0f; }
    __syncthreads();
    if (wid == 0) {
        float mm = sRed[lane];
#pragma unroll
        for (int o = 16; o; o >>= 1) mm = fmaxf(mm, __shfl_xor_sync(0xffffffffu, mm, o));
        if (lane == 0) sM = mm;
    }
    __syncthreads();
    float M = sM;

    // pass 2: exp + marginal sums over i/j/k
    int j = wid, k = lane;
    float part = 0.0f;
    const float* sp = s + j * 32 + k;
    for (int i = 0; i < 32; i++) {
        float v = expf(sp[i << 10] - M);
        part += v;
        float wv = v;
#pragma unroll
        for (int o = 16; o; o >>= 1) wv += __shfl_xor_sync(0xffffffffu, wv, o);
        if (lane == 0) atomicAdd(&sA0[i], wv);
    }
    float ws = part;
#pragma unroll
    for (int o = 16; o; o >>= 1) ws += __shfl_xor_sync(0xffffffffu, ws, o);
    if (lane == 0) sA1[j] = ws;
    atomicAdd(&sA2[k], part);
    __syncthreads();

    if (wid == 0) {
        float z = sA0[lane];
#pragma unroll
        for (int o = 16; o; o >>= 1) z += __shfl_xor_sync(0xffffffffu, z, o);
        if (lane == 0) sZ = z;
    }
    __syncthreads();
    float invZ = 1.0f / sZ;

    // subgoals[b,h,d] = (A_h @ rel)[d] / Z
    if (tid < 3 * DD) {
        int h = tid >> 7, d = tid & 127;
        const float* A = (h == 0) ? sA0 : ((h == 1) ? sA1 : sA2);
        float acc = 0.0f;
#pragma unroll
        for (int r = 0; r < RR; r++) acc += A[r] * __ldg(&rel[r * DD + d]);
        int o = b * (3 * DD) + tid;
        if (o < out_size) out[o] = acc * invZ;
    }
}

// ---------------- kernel F: mask fill (ones) ----------------
__global__ void fill_kernel(float* out, int start, int total) {
    int i = start + blockIdx.x * blockDim.x + threadIdx.x;
    if (i < total) out[i] = 1.0f;
}

// ---------------- launch ----------------
extern "C" void kernel_launch(void* const* d_in, const int* in_sizes, int n_in,
                              void* d_out, int out_size) {
    const float* query = (const float*)d_in[0];
    const float* rel   = (const float*)d_in[1];
    const float* w1    = (const float*)d_in[2];
    const float* b1    = (const float*)d_in[3];
    const float* w2    = (const float*)d_in[4];
    // d_in[5] = b2: constant score shift, softmax-invariant -> unused
    float* out = (float*)d_out;

    cudaFuncSetAttribute(score_kernel, cudaFuncAttributeMaxDynamicSharedMemorySize, SMEM_BYTES);

    qb_kernel<<<BB, DD>>>(query, w1, b1);
    score_kernel<<<N_TOT / TN, 256, SMEM_BYTES>>>(rel, w1, w2);
    softmax_kernel<<<BB, 1024>>>(rel, out, out_size);

    int start = BB * 3 * DD;  // 12288 subgoal floats
    if (out_size > start) {
        int rem = out_size - start;
        fill_kernel<<<(rem + 255) / 256, 256>>>(out, start, out_size);
    }
}

// round 3
// speedup vs baseline: 1.1994x; 1.1994x over previous
#include <cuda_runtime.h>
#include <cuda_bf16.h>
#include <cstdint>
#include <math.h>

#define BB 32      // batch
#define DD 128     // dim
#define RR 32      // relations
#define NBLK 256   // score blocks
#define TN 128     // n-rows per block

// ---------------- scratch ----------------
__device__ float g_qb[BB * DD];              // qh + b1
__device__ float g_part[BB * NBLK * 40];     // per-block marginal partials

// ---------------- helpers ----------------
__device__ __forceinline__ uint32_t f2tf32(float x) {
    uint32_t r; asm("cvt.rna.tf32.f32 %0, %1;" : "=r"(r) : "f"(x)); return r;
}
__device__ __forceinline__ unsigned long long pk2(float lo, float hi) {
    unsigned long long d; asm("mov.b64 %0, {%1, %2};" : "=l"(d) : "f"(lo), "f"(hi)); return d;
}
__device__ __forceinline__ void upk2(unsigned long long v, float& lo, float& hi) {
    asm("mov.b64 {%0, %1}, %2;" : "=f"(lo), "=f"(hi) : "l"(v));
}
__device__ __forceinline__ unsigned long long add2(unsigned long long a, unsigned long long b) {
    unsigned long long d; asm("add.rn.f32x2 %0, %1, %2;" : "=l"(d) : "l"(a), "l"(b)); return d;
}
__device__ __forceinline__ unsigned long long fma2(unsigned long long a, unsigned long long b,
                                                   unsigned long long c) {
    unsigned long long d; asm("fma.rn.f32x2 %0, %1, %2, %3;" : "=l"(d) : "l"(a), "l"(b), "l"(c)); return d;
}
__device__ __forceinline__ void mma_tf32(float c[4], uint32_t a0, uint32_t a1, uint32_t a2,
                                         uint32_t a3, uint32_t b0, uint32_t b1) {
    asm volatile(
        "mma.sync.aligned.m16n8k8.row.col.f32.tf32.tf32.f32 "
        "{%0,%1,%2,%3}, {%4,%5,%6,%7}, {%8,%9}, {%0,%1,%2,%3};\n"
        : "+f"(c[0]), "+f"(c[1]), "+f"(c[2]), "+f"(c[3])
        : "r"(a0), "r"(a1), "r"(a2), "r"(a3), "r"(b0), "r"(b1));
}

// ---------------- kernel A: qb[b,d] = (query @ w1q)[b,d] + b1[d] ----------------
__global__ void qb_kernel(const float* __restrict__ query,
                          const float* __restrict__ w1,
                          const float* __restrict__ b1) {
    int b = blockIdx.x, d = threadIdx.x;
    __shared__ float sq[DD];
    sq[d] = query[b * DD + d];
    __syncthreads();
    float acc = b1[d];
#pragma unroll 8
    for (int k = 0; k < DD; k++) acc += sq[k] * __ldg(&w1[k * DD + d]);
    g_qb[b * DD + d] = acc;
}

// ---------------- kernel B: body -> tf32 mma GEMM -> fused relu-dot -> exp -> marginals ----------------
#define SB 136  // padded stride (136 % 32 == 8 -> conflict-free fragment loads)
#define OFF_W   17408
#define OFF_QB  34816
#define OFF_REL 38912
#define OFF_W2  43136
#define OFF_EXP 43264
#define SMEM_FLOATS 47360
#define SMEM_BYTES (SMEM_FLOATS * 4)

__global__ __launch_bounds__(256, 1)
void score_kernel(const float* __restrict__ rel,
                  const float* __restrict__ w1,
                  const float* __restrict__ w2) {
    extern __shared__ float sm[];
    float* sBody = sm;             // [128][SB] tf32 bits
    float* sW    = sm + OFF_W;     // [128][SB] tf32 bits (w1b)
    float* sQb   = sm + OFF_QB;    // [32][128]
    float* sRel  = sm + OFF_REL;   // [32][132]
    float* sW2   = sm + OFF_W2;    // [128]
    float* sExp  = sm + OFF_EXP;   // [32][128]

    int tid = threadIdx.x;
    int blk = blockIdx.x;
    int wid = tid >> 5, lane = tid & 31;
    int g = lane >> 2, t = lane & 3;

    // ---- cooperative loads ----
    const float* w1b = w1 + DD * DD;
    for (int idx = tid; idx < DD * DD; idx += 256) {
        int d = idx >> 7, o = idx & 127;
        sW[d * SB + o] = __uint_as_float(f2tf32(w1b[idx]));
    }
    for (int idx = tid; idx < RR * DD; idx += 256) {
        int r = idx >> 7, d = idx & 127;
        sRel[r * 132 + d] = rel[idx];
    }
    for (int idx = tid; idx < BB * DD; idx += 256) sQb[idx] = g_qb[idx];
    if (tid < DD) sW2[tid] = w2[tid];
    __syncthreads();

    // ---- body[nn][d] = rel_i[d]*rel_j[d]*rel_k[d] (tf32) ----
    int iblk = blk >> 3;
    const float* relI = &sRel[iblk * 132];
#pragma unroll 4
    for (int it = 0; it < 64; it++) {
        int idx = tid + it * 256;
        int nn = idx >> 7, d = idx & 127;
        int j = ((blk << 2) + (nn >> 5)) & 31;
        int k = nn & 31;
        float v = relI[d] * sRel[j * 132 + d] * sRel[k * 132 + d];
        sBody[nn * SB + d] = __uint_as_float(f2tf32(v));
    }
    __syncthreads();

    // ---- GEMM: bh[nn, o] = body @ w1b, warp wid owns rows [wid*16, wid*16+16), all 128 o ----
    int m0 = wid << 4;
    float acc[16][4];
#pragma unroll
    for (int nt = 0; nt < 16; nt++)
#pragma unroll
        for (int v = 0; v < 4; v++) acc[nt][v] = 0.0f;

    const uint32_t* bodyU = (const uint32_t*)sBody;
    const uint32_t* wU    = (const uint32_t*)sW;
    for (int k0 = 0; k0 < DD; k0 += 8) {
        uint32_t a0 = bodyU[(m0 + g) * SB + k0 + t];
        uint32_t a1 = bodyU[(m0 + g + 8) * SB + k0 + t];
        uint32_t a2 = bodyU[(m0 + g) * SB + k0 + t + 4];
        uint32_t a3 = bodyU[(m0 + g + 8) * SB + k0 + t + 4];
#pragma unroll
        for (int nt = 0; nt < 16; nt++) {
            uint32_t b0 = wU[(k0 + t) * SB + (nt << 3) + g];
            uint32_t b1 = wU[(k0 + t + 4) * SB + (nt << 3) + g];
            mma_tf32(acc[nt], a0, a1, a2, a3, b0, b1);
        }
    }

    // ---- pack accumulators + w2/2 pairs ----
    unsigned long long accp[16][2], w2h[16];
#pragma unroll
    for (int nt = 0; nt < 16; nt++) {
        accp[nt][0] = pk2(acc[nt][0], acc[nt][1]);   // row g,   cols 2t, 2t+1
        accp[nt][1] = pk2(acc[nt][2], acc[nt][3]);   // row g+8
        int c0 = (nt << 3) + 2 * t;
        w2h[nt] = pk2(0.5f * sW2[c0], 0.5f * sW2[c0 + 1]);
    }

    // ---- fused score: relu(qb+bh)·w2 summed over o, then exp ----
    const unsigned long long MABS = 0x7FFFFFFF7FFFFFFFull;
    for (int b = 0; b < BB; b++) {
        unsigned long long s0 = 0ull, s1 = 0ull;
        const float* qrow = &sQb[b * DD];
#pragma unroll
        for (int nt = 0; nt < 16; nt++) {
            unsigned long long q = *(const unsigned long long*)&qrow[(nt << 3) + 2 * t];
            unsigned long long t0 = add2(q, accp[nt][0]);
            unsigned long long t1 = add2(q, accp[nt][1]);
            unsigned long long a0 = t0 & MABS;
            unsigned long long a1 = t1 & MABS;
            s0 = fma2(t0, w2h[nt], s0);
            s0 = fma2(a0, w2h[nt], s0);
            s1 = fma2(t1, w2h[nt], s1);
            s1 = fma2(a1, w2h[nt], s1);
        }
        float l0, h0, l1, h1;
        upk2(s0, l0, h0);
        upk2(s1, l1, h1);
        float sc0 = l0 + h0, sc1 = l1 + h1;
        sc0 += __shfl_xor_sync(0xffffffffu, sc0, 1);
        sc0 += __shfl_xor_sync(0xffffffffu, sc0, 2);
        sc1 += __shfl_xor_sync(0xffffffffu, sc1, 1);
        sc1 += __shfl_xor_sync(0xffffffffu, sc1, 2);
        float e0 = __expf(sc0), e1 = __expf(sc1);
        if (t == 0) {
            sExp[b * 128 + m0 + g]     = e0;
            sExp[b * 128 + m0 + g + 8] = e1;
        }
    }
    __syncthreads();

    // ---- per-block marginal partials (deterministic, no atomics) ----
    // block covers i = blk>>3 (fixed), j = 4*(blk&7)+jg (jg=nn>>5), k = nn&31
    for (int bb = 0; bb < 4; bb++) {
        int b = (wid << 2) + bb;
        float v0 = sExp[b * 128 +  0 + lane];
        float v1 = sExp[b * 128 + 32 + lane];
        float v2 = sExp[b * 128 + 64 + lane];
        float v3 = sExp[b * 128 + 96 + lane];
        float* base = &g_part[(b * NBLK + blk) * 40];
        base[lane] = v0 + v1 + v2 + v3;   // k-partial
        float t0 = v0, t1 = v1, t2 = v2, t3 = v3;
#pragma unroll
        for (int o = 16; o; o >>= 1) {
            t0 += __shfl_xor_sync(0xffffffffu, t0, o);
            t1 += __shfl_xor_sync(0xffffffffu, t1, o);
            t2 += __shfl_xor_sync(0xffffffffu, t2, o);
            t3 += __shfl_xor_sync(0xffffffffu, t3, o);
        }
        if (lane == 0) {
            base[32] = t0; base[33] = t1; base[34] = t2; base[35] = t3;
            base[36] = t0 + t1 + t2 + t3;   // i-partial (block total)
        }
    }
}

// ---------------- kernel C: reduce partials -> subgoals + masks ----------------
__global__ __launch_bounds__(512)
void finalize_kernel(const float* __restrict__ rel,
                     float* __restrict__ out, int out_size) {
    int b = blockIdx.x, tid = threadIdx.x;
    __shared__ float sA[3][32];
    __shared__ float sZ;
    const float* base = &g_part[b * NBLK * 40];

    if (tid < 96) {
        int cls = tid >> 5, r = tid & 31;
        float s = 0.0f;
        if (cls == 0) {                    // Ai[i]: blocks 8i..8i+7, slot 36
            for (int u = 0; u < 8; u++) s += base[((r << 3) + u) * 40 + 36];
        } else if (cls == 1) {             // Aj[j]: blk = 8m + (j>>2), slot 32+(j&3)
            int bo = r >> 2, sl = 32 + (r & 3);
            for (int m = 0; m < 32; m++) s += base[((m << 3) + bo) * 40 + sl];
        } else {                           // Ak[k]: all 256 blocks, slot k
            for (int m = 0; m < 256; m++) s += base[m * 40 + r];
        }
        sA[cls][r] = s;
    }
    __syncthreads();
    if (tid == 0) {
        float z = 0.0f;
        for (int r = 0; r < 32; r++) z += sA[0][r];
        sZ = z;
    }
    __syncthreads();
    float invZ = 1.0f / sZ;

    if (tid < 3 * DD) {
        int h = tid >> 7, d = tid & 127;
        float a = 0.0f;
#pragma unroll
        for (int r = 0; r < RR; r++) a += sA[h][r] * __ldg(&rel[r * DD + d]);
        int o = b * (3 * DD) + tid;
        if (o < out_size) out[o] = a * invZ;
    } else {
        // mask tail: all blocks write the same 1.0f values (benign identical writes)
        int m = tid - 3 * DD;              // 0..127
        int o = BB * 3 * DD + m;
        if (o < out_size) out[o] = 1.0f;
    }
}

// ---------------- launch ----------------
extern "C" void kernel_launch(void* const* d_in, const int* in_sizes, int n_in,
                              void* d_out, int out_size) {
    const float* query = (const float*)d_in[0];
    const float* rel   = (const float*)d_in[1];
    const float* w1    = (const float*)d_in[2];
    const float* b1    = (const float*)d_in[3];
    const float* w2    = (const float*)d_in[4];
    // d_in[5] = b2: constant score shift, softmax-invariant -> unused
    float* out = (float*)d_out;

    cudaFuncSetAttribute(score_kernel, cudaFuncAttributeMaxDynamicSharedMemorySize, SMEM_BYTES);

    qb_kernel<<<BB, DD>>>(query, w1, b1);
    score_kernel<<<NBLK, 256, SMEM_BYTES>>>(rel, w1, w2);
    finalize_kernel<<<BB, 512>>>(rel, out, out_size);
}

// round 5
// speedup vs baseline: 1.7702x; 1.4759x over previous
#include <cuda_runtime.h>
#include <cuda_bf16.h>
#include <cstdint>
#include <math.h>

#define BB 32
#define DD 128
#define RR 32
#define NBLK 256

// ---------------- scratch ----------------
__device__ float g_qb[BB * DD];
__device__ float g_part[BB * NBLK * 40];

// ---------------- helpers ----------------
__device__ __forceinline__ uint32_t pkbf2(float lo, float hi) {
    __nv_bfloat162 h = __floats2bfloat162_rn(lo, hi);   // .x = lo (lower 16b), .y = hi
    return *reinterpret_cast<uint32_t*>(&h);
}
__device__ __forceinline__ unsigned long long pk2(float lo, float hi) {
    unsigned long long d; asm("mov.b64 %0, {%1, %2};" : "=l"(d) : "f"(lo), "f"(hi)); return d;
}
__device__ __forceinline__ void upk2(unsigned long long v, float& lo, float& hi) {
    asm("mov.b64 {%0, %1}, %2;" : "=f"(lo), "=f"(hi) : "l"(v));
}
__device__ __forceinline__ unsigned long long add2(unsigned long long a, unsigned long long b) {
    unsigned long long d; asm("add.rn.f32x2 %0, %1, %2;" : "=l"(d) : "l"(a), "l"(b)); return d;
}
__device__ __forceinline__ unsigned long long fma2(unsigned long long a, unsigned long long b,
                                                   unsigned long long c) {
    unsigned long long d; asm("fma.rn.f32x2 %0, %1, %2, %3;" : "=l"(d) : "l"(a), "l"(b), "l"(c)); return d;
}
__device__ __forceinline__ void mma_bf16(float c[4], uint32_t a0, uint32_t a1, uint32_t a2,
                                         uint32_t a3, uint32_t b0, uint32_t b1) {
    asm volatile(
        "mma.sync.aligned.m16n8k16.row.col.f32.bf16.bf16.f32 "
        "{%0,%1,%2,%3}, {%4,%5,%6,%7}, {%8,%9}, {%0,%1,%2,%3};\n"
        : "+f"(c[0]), "+f"(c[1]), "+f"(c[2]), "+f"(c[3])
        : "r"(a0), "r"(a1), "r"(a2), "r"(a3), "r"(b0), "r"(b1));
}

// ---------------- kernel A: qb = query @ w1q + b1 (latency-optimized) ----------------
__global__ __launch_bounds__(128)
void qb_kernel(const float* __restrict__ query,
               const float* __restrict__ w1,
               const float* __restrict__ b1) {
    int b = blockIdx.x, d = threadIdx.x;
    __shared__ float sq[DD];
    sq[d] = query[b * DD + d];
    __syncthreads();
    float a0 = b1[d], a1 = 0.0f, a2 = 0.0f, a3 = 0.0f;
#pragma unroll
    for (int k = 0; k < DD; k += 4) {
        a0 += sq[k    ] * __ldg(&w1[(k    ) * DD + d]);
        a1 += sq[k + 1] * __ldg(&w1[(k + 1) * DD + d]);
        a2 += sq[k + 2] * __ldg(&w1[(k + 2) * DD + d]);
        a3 += sq[k + 3] * __ldg(&w1[(k + 3) * DD + d]);
    }
    g_qb[b * DD + d] = (a0 + a1) + (a2 + a3);
}

// ---------------- kernel B: body -> bf16 mma -> fused relu-dot -> exp -> marginals ----------------
// smem word (u32/float) layout:
#define OFF_BODYH 0        // 128 x 72 u32 (bf16x2 k-pairs)   [reused as sP0/sP1 after GEMM]
#define OFF_WH    9216     // 64 x 136 u32 (bf16x2 pairs x o)
#define OFF_QB    17920    // 32 x 128
#define OFF_REL   22016    // 32 x 132
#define OFF_W2    26240    // 128
#define OFF_EXP   26368    // 32 x 128
#define OFF_QDW   30464    // 32
#define SMEM_WORDS 30496
#define SMEM_BYTES (SMEM_WORDS * 4)

__global__ __launch_bounds__(512, 1)
void score_kernel(const float* __restrict__ rel,
                  const float* __restrict__ w1,
                  const float* __restrict__ w2) {
    extern __shared__ float sm[];
    uint32_t* sBodyH = (uint32_t*)sm;              // [128][72]
    uint32_t* sWH    = (uint32_t*)(sm + OFF_WH);   // [64][136]
    float* sQb  = sm + OFF_QB;
    float* sRel = sm + OFF_REL;
    float* sW2  = sm + OFF_W2;
    float* sExp = sm + OFF_EXP;
    float* sQdw = sm + OFF_QDW;
    float* sP0  = sm;                              // [32][128] overlays sBodyH
    float* sP1  = sm + 4096;

    int tid = threadIdx.x;
    int blk = blockIdx.x;
    int wid = tid >> 5, lane = tid & 31;
    int g = lane >> 2, t = lane & 3;
    int m0 = (wid >> 1) << 4;     // 8 row-stripes of 16
    int h  = wid & 1;             // column half
    int nt0 = h << 3;             // nt in [nt0, nt0+8)

    // ---- cooperative loads ----
    const float* w1b = w1 + DD * DD;
    for (int idx = tid; idx < 64 * DD; idx += 512) {
        int p = idx >> 7, o = idx & 127;
        sWH[p * 136 + o] = pkbf2(w1b[(2 * p) * DD + o], w1b[(2 * p + 1) * DD + o]);
    }
    for (int idx = tid; idx < RR * DD; idx += 512) {
        int r = idx >> 7, d = idx & 127;
        sRel[r * 132 + d] = rel[idx];
    }
    for (int idx = tid; idx < BB * DD; idx += 512) sQb[idx] = g_qb[idx];
    if (tid < DD) sW2[tid] = w2[tid];
    __syncthreads();

    // ---- body (bf16x2 pairs) + qdotw ----
    int iblk = blk >> 3;
    const float* relI = &sRel[iblk * 132];
#pragma unroll 4
    for (int it = 0; it < 16; it++) {
        int idx = tid + it * 512;                 // over 128n x 64 pairs
        int nn = idx >> 6, p = idx & 63;
        int j = ((blk << 2) + (nn >> 5)) & 31;
        int k = nn & 31;
        int d0 = 2 * p, d1 = 2 * p + 1;
        float v0 = relI[d0] * sRel[j * 132 + d0] * sRel[k * 132 + d0];
        float v1 = relI[d1] * sRel[j * 132 + d1] * sRel[k * 132 + d1];
        sBodyH[nn * 72 + p] = pkbf2(v0, v1);
    }
    if (tid < BB) {
        float s = 0.0f;
#pragma unroll 16
        for (int d = 0; d < DD; d++) s += sQb[tid * DD + d] * sW2[d];
        sQdw[tid] = 0.5f * s;
    }
    __syncthreads();

    // ---- GEMM: warp = rows [m0,m0+16) x cols [h*64, h*64+64) ----
    float acc[8][4];
#pragma unroll
    for (int q = 0; q < 8; q++)
#pragma unroll
        for (int v = 0; v < 4; v++) acc[q][v] = 0.0f;

    for (int kp0 = 0; kp0 < 64; kp0 += 8) {
        uint32_t a0 = sBodyH[(m0 + g    ) * 72 + kp0 + t];
        uint32_t a1 = sBodyH[(m0 + g + 8) * 72 + kp0 + t];
        uint32_t a2 = sBodyH[(m0 + g    ) * 72 + kp0 + t + 4];
        uint32_t a3 = sBodyH[(m0 + g + 8) * 72 + kp0 + t + 4];
#pragma unroll
        for (int q = 0; q < 8; q++) {
            int col = ((nt0 + q) << 3) + g;
            uint32_t b0 = sWH[(kp0 + t    ) * 136 + col];
            uint32_t b1 = sWH[(kp0 + t + 4) * 136 + col];
            mma_bf16(acc[q], a0, a1, a2, a3, b0, b1);
        }
    }

    // ---- pack acc + w2/2; linear part folded into init ----
    unsigned long long accp[8][2], w2h[8];
    unsigned long long lin0 = 0ull, lin1 = 0ull;
#pragma unroll
    for (int q = 0; q < 8; q++) {
        accp[q][0] = pk2(acc[q][0], acc[q][1]);
        accp[q][1] = pk2(acc[q][2], acc[q][3]);
        int c0 = ((nt0 + q) << 3) + 2 * t;
        w2h[q] = pk2(0.5f * sW2[c0], 0.5f * sW2[c0 + 1]);
        lin0 = fma2(accp[q][0], w2h[q], lin0);
        lin1 = fma2(accp[q][1], w2h[q], lin1);
    }
    __syncthreads();   // sBodyH reads done; region becomes sP0/sP1

    // ---- fused score (abs part only) per batch ----
    const unsigned long long MABS = 0x7FFFFFFF7FFFFFFFull;
    for (int b = 0; b < BB; b++) {
        unsigned long long s0 = lin0, s1 = lin1;
        const float* qrow = &sQb[b * DD];
#pragma unroll
        for (int q = 0; q < 8; q++) {
            unsigned long long qv = *(const unsigned long long*)&qrow[((nt0 + q) << 3) + 2 * t];
            unsigned long long t0 = add2(qv, accp[q][0]) & MABS;
            unsigned long long t1 = add2(qv, accp[q][1]) & MABS;
            s0 = fma2(t0, w2h[q], s0);
            s1 = fma2(t1, w2h[q], s1);
        }
        float l0, h0, l1, h1;
        upk2(s0, l0, h0);
        upk2(s1, l1, h1);
        float sc0 = l0 + h0, sc1 = l1 + h1;
        sc0 += __shfl_xor_sync(0xffffffffu, sc0, 1);
        sc0 += __shfl_xor_sync(0xffffffffu, sc0, 2);
        sc1 += __shfl_xor_sync(0xffffffffu, sc1, 1);
        sc1 += __shfl_xor_sync(0xffffffffu, sc1, 2);
        if (t == 0) {
            float* sP = h ? sP1 : sP0;
            sP[b * 128 + m0 + g]     = sc0;
            sP[b * 128 + m0 + g + 8] = sc1;
        }
    }
    __syncthreads();

    // ---- combine halves + exp ----
    for (int x = tid; x < BB * 128; x += 512) {
        int b = x >> 7;
        sExp[x] = __expf(sP0[x] + sP1[x] + sQdw[b]);
    }
    __syncthreads();

    // ---- per-block marginal partials (deterministic) ----
    for (int bb = 0; bb < 2; bb++) {
        int b = (wid << 1) + bb;
        float v0 = sExp[b * 128 +  0 + lane];
        float v1 = sExp[b * 128 + 32 + lane];
        float v2 = sExp[b * 128 + 64 + lane];
        float v3 = sExp[b * 128 + 96 + lane];
        float* base = &g_part[(b * NBLK + blk) * 40];
        base[lane] = v0 + v1 + v2 + v3;   // k-partial
        float t0 = v0, t1 = v1, t2 = v2, t3 = v3;
#pragma unroll
        for (int o = 16; o; o >>= 1) {
            t0 += __shfl_xor_sync(0xffffffffu, t0, o);
            t1 += __shfl_xor_sync(0xffffffffu, t1, o);
            t2 += __shfl_xor_sync(0xffffffffu, t2, o);
            t3 += __shfl_xor_sync(0xffffffffu, t3, o);
        }
        if (lane == 0) {
            base[32] = t0; base[33] = t1; base[34] = t2; base[35] = t3;
            base[36] = t0 + t1 + t2 + t3;   // i-partial
        }
    }
}

// ---------------- kernel C: reduce partials -> subgoals + masks ----------------
__global__ __launch_bounds__(512)
void finalize_kernel(const float* __restrict__ rel,
                     float* __restrict__ out, int out_size) {
    int b = blockIdx.x, tid = threadIdx.x;
    int r = tid & 31, gg = tid >> 5;   // 16 groups
    __shared__ float pK[16][33], pJ[16][33], pI[8][33];
    __shared__ float sA[3][32];
    __shared__ float sZ;
    const float* base = &g_part[b * NBLK * 40];

    // partial sums
    float sk = 0.0f;
#pragma unroll
    for (int m = gg; m < 256; m += 16) sk += base[m * 40 + r];
    pK[gg][r] = sk;

    float sj = base[((2 * gg    ) * 8 + (r >> 2)) * 40 + 32 + (r & 3)]
             + base[((2 * gg + 1) * 8 + (r >> 2)) * 40 + 32 + (r & 3)];
    pJ[gg][r] = sj;

    if (gg < 8) pI[gg][r] = base[(r * 8 + gg) * 40 + 36];
    __syncthreads();

    if (tid < 96) {
        int cls = tid >> 5, rr = tid & 31;
        float s = 0.0f;
        if (cls == 0) { for (int u = 0; u < 16; u++) s += pK[u][rr]; }
        else if (cls == 1) { for (int u = 0; u < 16; u++) s += pJ[u][rr]; }
        else { for (int u = 0; u < 8; u++) s += pI[u][rr]; }
        sA[cls][rr] = s;
    }
    __syncthreads();
    if (tid == 0) {
        float z = 0.0f;
        for (int rr = 0; rr < 32; rr++) z += sA[2][rr];
        sZ = z;
    }
    __syncthreads();
    float invZ = 1.0f / sZ;

    if (tid < 3 * DD) {
        int hh = tid >> 7, d = tid & 127;
        float a = 0.0f;
#pragma unroll
        for (int rr = 0; rr < RR; rr++) a += sA[hh][rr] * __ldg(&rel[rr * DD + d]);
        int o = b * (3 * DD) + tid;
        if (o < out_size) out[o] = a * invZ;
    } else {
        int m = tid - 3 * DD;   // 0..127
        int o = BB * 3 * DD + m;
        if (o < out_size) out[o] = 1.0f;
    }
}

// ---------------- launch ----------------
extern "C" void kernel_launch(void* const* d_in, const int* in_sizes, int n_in,
                              void* d_out, int out_size) {
    const float* query = (const float*)d_in[0];
    const float* rel   = (const float*)d_in[1];
    const float* w1    = (const float*)d_in[2];
    const float* b1    = (const float*)d_in[3];
    const float* w2    = (const float*)d_in[4];
    float* out = (float*)d_out;

    cudaFuncSetAttribute(score_kernel, cudaFuncAttributeMaxDynamicSharedMemorySize, SMEM_BYTES);

    qb_kernel<<<BB, DD>>>(query, w1, b1);
    score_kernel<<<NBLK, 512, SMEM_BYTES>>>(rel, w1, w2);
    finalize_kernel<<<BB, 512>>>(rel, out, out_size);
}